// round 11
// baseline (speedup 1.0000x reference)
#include <cuda_runtime.h>
#include <math.h>

// Problem constants (fixed shapes from reference setup_inputs)
#define B_SZ 4096
#define L_SZ 200
#define D_SZ 256
#define MB_BLOCKS 64                // gemm m-tiles == BN partial count
#define HEAD_CTAS (B_SZ / 8)        // 512
static __device__ __constant__ float kInvB = 1.0f / (float)B_SZ;
#define BN_EPS 1e-5f

// ---- scratch (device globals; no allocation allowed) ----
__device__ float g_pooled[(size_t)B_SZ * D_SZ];   // 4 MB
__device__ float g_z[(size_t)B_SZ * D_SZ];        // 4 MB
__device__ float g_psum[MB_BLOCKS * D_SZ];
__device__ float g_psq[MB_BLOCKS * D_SZ];
__device__ float g_scale[D_SZ];
__device__ float g_shift[D_SZ];
__device__ float g_bce[HEAD_CTAS];
__device__ unsigned int g_ctr_gemm;   // zero-initialized; last CTA resets
__device__ unsigned int g_ctr_head;

// ---- packed f32x2 helpers (Blackwell) ----
__device__ __forceinline__ unsigned long long pk2(float lo, float hi) {
    unsigned long long r;
    asm("mov.b64 %0, {%1, %2};" : "=l"(r) : "f"(lo), "f"(hi));
    return r;
}
__device__ __forceinline__ void upk2(unsigned long long v, float& lo, float& hi) {
    asm("mov.b64 {%0, %1}, %2;" : "=f"(lo), "=f"(hi) : "l"(v));
}
__device__ __forceinline__ unsigned long long fma2(unsigned long long a,
                                                   unsigned long long b,
                                                   unsigned long long c) {
    unsigned long long d;
    asm("fma.rn.f32x2 %0, %1, %2, %3;" : "=l"(d) : "l"(a), "l"(b), "l"(c));
    return d;
}

// ============================================================================
// K1: ragged gather + mean pool.  One CTA per batch row, 256 threads.
// (Exact R5 form: measured at the LTS chip-throughput wall, ~35.7us.)
// ============================================================================
__global__ void __launch_bounds__(256) pool_kernel(const int* __restrict__ tokens,
                                                   const int* __restrict__ lengths,
                                                   const float* __restrict__ emb) {
    const int b = blockIdx.x;
    const int tid = threadIdx.x;
    __shared__ int s_tok[L_SZ];
    const int len = lengths[b];
    for (int i = tid; i < len; i += 256) s_tok[i] = tokens[b * L_SZ + i];
    __syncthreads();

    const int sub = tid >> 6;   // 0..3 : which token of the group of 4
    const int q   = tid & 63;   // which float4 of the 256-wide embedding

    float4 acc = make_float4(0.f, 0.f, 0.f, 0.f);
    #pragma unroll 4
    for (int l = sub; l < len; l += 4) {
        const float4* row = reinterpret_cast<const float4*>(emb + (size_t)s_tok[l] * D_SZ);
        float4 v = __ldg(row + q);
        acc.x += v.x; acc.y += v.y; acc.z += v.z; acc.w += v.w;
    }

    __shared__ float4 s_acc[256];
    s_acc[tid] = acc;
    __syncthreads();
    if (tid < 64) {
        float4 a = s_acc[tid];
        float4 c = s_acc[tid + 64];
        float4 d = s_acc[tid + 128];
        float4 e = s_acc[tid + 192];
        const float inv = 1.0f / (float)len;
        float4 r;
        r.x = (a.x + c.x + d.x + e.x) * inv;
        r.y = (a.y + c.y + d.y + e.y) * inv;
        r.z = (a.z + c.z + d.z + e.z) * inv;
        r.w = (a.w + c.w + d.w + e.w) * inv;
        reinterpret_cast<float4*>(g_pooled + (size_t)b * D_SZ)[tid] = r;
    }
}

// ============================================================================
// K2: z = pooled @ W1^T + b1 + BN partial stats + last-CTA finalize.
// 64x64 tile, BK=16, 256 threads.  Inner loop: 8 FFMA2 + 5 LDS per k-step,
// ZERO packing movs (A pre-duplicated in SMEM as 64-bit pairs; B pairs read
// directly as the low/high halves of an LDS.128).
// ============================================================================
__global__ void __launch_bounds__(256) gemm_kernel(const float* __restrict__ W1,
                                                   const float* __restrict__ b1,
                                                   const float* __restrict__ gamma,
                                                   const float* __restrict__ beta) {
    __shared__ unsigned long long As2[16][64];  // (a,a) dup pairs, 8KB
    __shared__ float Bs[16][68];                // Bs[k][n] (+4 pad; 272B rows, 16B-aligned)
    __shared__ float s_sum[16][64];
    __shared__ float s_sq[16][64];

    const int tid = threadIdx.x;
    const int tx = tid & 15, ty = tid >> 4;
    const int m0 = blockIdx.x * 64;
    const int n0 = blockIdx.y * 64;
    const int lr = tid >> 2;            // 0..63 tile row
    const int lk = (tid & 3) << 2;      // 0,4,8,12 k-offset

    unsigned long long c2[4][2];
    #pragma unroll
    for (int i = 0; i < 4; i++) { c2[i][0] = 0ull; c2[i][1] = 0ull; }

    for (int k0 = 0; k0 < D_SZ; k0 += 16) {
        float4 av = *reinterpret_cast<const float4*>(g_pooled + (size_t)(m0 + lr) * D_SZ + k0 + lk);
        float4 bv = *reinterpret_cast<const float4*>(W1 + (size_t)(n0 + lr) * D_SZ + k0 + lk);
        As2[lk + 0][lr] = pk2(av.x, av.x);
        As2[lk + 1][lr] = pk2(av.y, av.y);
        As2[lk + 2][lr] = pk2(av.z, av.z);
        As2[lk + 3][lr] = pk2(av.w, av.w);
        Bs[lk + 0][lr] = bv.x; Bs[lk + 1][lr] = bv.y; Bs[lk + 2][lr] = bv.z; Bs[lk + 3][lr] = bv.w;
        __syncthreads();

        #pragma unroll
        for (int k = 0; k < 16; k++) {
            const unsigned long long* arow = &As2[k][ty << 2];
            ulonglong2 bb = *reinterpret_cast<const ulonglong2*>(&Bs[k][tx << 2]);
            #pragma unroll
            for (int i = 0; i < 4; i++) {
                unsigned long long ad = arow[i];
                c2[i][0] = fma2(ad, bb.x, c2[i][0]);
                c2[i][1] = fma2(ad, bb.y, c2[i][1]);
            }
        }
        __syncthreads();
    }

    const int col = n0 + (tx << 2);
    float4 bias = *reinterpret_cast<const float4*>(b1 + col);
    float cs[4] = {0.f, 0.f, 0.f, 0.f};
    float cq[4] = {0.f, 0.f, 0.f, 0.f};
    #pragma unroll
    for (int i = 0; i < 4; i++) {
        float v[4];
        upk2(c2[i][0], v[0], v[1]);
        upk2(c2[i][1], v[2], v[3]);
        v[0] += bias.x; v[1] += bias.y; v[2] += bias.z; v[3] += bias.w;
        #pragma unroll
        for (int c = 0; c < 4; c++) {
            cs[c] += v[c];
            cq[c] = fmaf(v[c], v[c], cq[c]);
        }
        const int row = m0 + (ty << 2) + i;
        float4 o = make_float4(v[0], v[1], v[2], v[3]);
        *reinterpret_cast<float4*>(g_z + (size_t)row * D_SZ + col) = o;
    }
    // column partial stats: reduce over the 16 ty-groups
    #pragma unroll
    for (int c = 0; c < 4; c++) {
        s_sum[ty][(tx << 2) + c] = cs[c];
        s_sq[ty][(tx << 2) + c] = cq[c];
    }
    __syncthreads();
    if (tid < 64) {
        float s = 0.f, sq = 0.f;
        #pragma unroll
        for (int j = 0; j < 16; j++) { s += s_sum[j][tid]; sq += s_sq[j][tid]; }
        g_psum[blockIdx.x * D_SZ + n0 + tid] = s;
        g_psq[blockIdx.x * D_SZ + n0 + tid] = sq;
    }

    // ---- last-CTA finalize: deterministic (fixed-order sums) ----
    __threadfence();
    __shared__ unsigned int s_ticket;
    if (tid == 0) s_ticket = atomicAdd(&g_ctr_gemm, 1u);
    __syncthreads();
    if (s_ticket == (unsigned)(gridDim.x * gridDim.y - 1)) {
        if (tid == 0) g_ctr_gemm = 0u;   // reset for next graph replay
        const int d = tid;               // 256 threads == 256 features
        float s = 0.f, sq = 0.f;
        #pragma unroll 8
        for (int i = 0; i < MB_BLOCKS; i++) {
            s  += g_psum[i * D_SZ + d];
            sq += g_psq[i * D_SZ + d];
        }
        const float mu = s * kInvB;
        const float var = sq * kInvB - mu * mu;
        const float rstd = rsqrtf(var + BN_EPS);
        const float sc = gamma[d] * rstd;
        g_scale[d] = sc;
        g_shift[d] = beta[d] - mu * sc;
    }
}

// ============================================================================
// K3: h = relu(scale*z + shift); logit = h.w2 + b2; per-CTA BCE partial;
// LAST CTA reduces 512 partials (fixed order) -> out[0].
// Warp per row, 8 rows/CTA, grid = 512.
// ============================================================================
__global__ void __launch_bounds__(256) head_kernel(const float* __restrict__ w2,
                                                   const float* __restrict__ b2,
                                                   const float* __restrict__ t,
                                                   float* __restrict__ out) {
    const int tid = threadIdx.x;
    const int warp = tid >> 5;
    const int lane = tid & 31;
    const int b = blockIdx.x * 8 + warp;

    const float4* zr = reinterpret_cast<const float4*>(g_z + (size_t)b * D_SZ);
    const float4* scv = reinterpret_cast<const float4*>(g_scale);
    const float4* shv = reinterpret_cast<const float4*>(g_shift);
    const float4* wv = reinterpret_cast<const float4*>(w2);

    float p = 0.f;
    #pragma unroll
    for (int half = 0; half < 2; half++) {
        const int q = lane + half * 32;
        float4 z = zr[q];
        float4 sc = __ldg(scv + q);
        float4 sh = __ldg(shv + q);
        float4 w = __ldg(wv + q);
        float h0 = fmaxf(fmaf(sc.x, z.x, sh.x), 0.f);
        float h1 = fmaxf(fmaf(sc.y, z.y, sh.y), 0.f);
        float h2 = fmaxf(fmaf(sc.z, z.z, sh.z), 0.f);
        float h3 = fmaxf(fmaf(sc.w, z.w, sh.w), 0.f);
        p += h0 * w.x + h1 * w.y + h2 * w.z + h3 * w.w;
    }
    #pragma unroll
    for (int off = 16; off > 0; off >>= 1)
        p += __shfl_down_sync(0xffffffffu, p, off);

    __shared__ float s_bce[8];
    if (lane == 0) {
        const float logit = p + b2[0];
        out[1 + b] = logit;
        const float tv = t[b];
        s_bce[warp] = fmaxf(logit, 0.f) - logit * tv + log1pf(expf(-fabsf(logit)));
    }
    __syncthreads();
    if (tid == 0) {
        float c = 0.f;
        #pragma unroll
        for (int i = 0; i < 8; i++) c += s_bce[i];
        g_bce[blockIdx.x] = c;
    }

    // ---- last-CTA loss reduce: deterministic fixed-order tree ----
    __threadfence();
    __shared__ unsigned int s_ticket;
    if (tid == 0) s_ticket = atomicAdd(&g_ctr_head, 1u);
    __syncthreads();
    if (s_ticket == (unsigned)(HEAD_CTAS - 1)) {
        if (tid == 0) g_ctr_head = 0u;   // reset for next graph replay
        __shared__ float red[256];
        red[tid] = g_bce[tid] + g_bce[tid + 256];
        __syncthreads();
        #pragma unroll
        for (int st = 128; st > 0; st >>= 1) {
            if (tid < st) red[tid] += red[tid + st];
            __syncthreads();
        }
        if (tid == 0) out[0] = red[0] * kInvB;
    }
}

// ============================================================================
extern "C" void kernel_launch(void* const* d_in, const int* in_sizes, int n_in,
                              void* d_out, int out_size) {
    const int*   tokens  = (const int*)d_in[0];
    const int*   lengths = (const int*)d_in[1];
    const float* t       = (const float*)d_in[2];
    const float* emb     = (const float*)d_in[3];
    const float* W1      = (const float*)d_in[4];
    const float* b1      = (const float*)d_in[5];
    const float* gamma   = (const float*)d_in[6];
    const float* beta    = (const float*)d_in[7];
    const float* w2      = (const float*)d_in[8];
    const float* b2      = (const float*)d_in[9];
    float* out = (float*)d_out;

    pool_kernel<<<B_SZ, 256>>>(tokens, lengths, emb);
    gemm_kernel<<<dim3(B_SZ / 64, D_SZ / 64), 256>>>(W1, b1, gamma, beta);
    head_kernel<<<HEAD_CTAS, 256>>>(w2, b2, t, out);
}

// round 12
// speedup vs baseline: 1.0575x; 1.0575x over previous
#include <cuda_runtime.h>
#include <math.h>

// Problem constants (fixed shapes from reference setup_inputs)
#define B_SZ 4096
#define L_SZ 200
#define D_SZ 256
#define HEAD_CTAS (B_SZ / 8)        // 512
static __device__ __constant__ float kInvB = 1.0f / (float)B_SZ;
#define BN_EPS 1e-5f

// ---- scratch (device globals; no allocation allowed) ----
__device__ float g_pooled[(size_t)B_SZ * D_SZ];   // 4 MB
__device__ float g_z[(size_t)B_SZ * D_SZ];        // 4 MB
__device__ float g_zp0[(size_t)B_SZ * D_SZ];      // 4 MB  (split-K partial 0)
__device__ float g_zp1[(size_t)B_SZ * D_SZ];      // 4 MB  (split-K partial 1)
__device__ float g_psum[64 * D_SZ];
__device__ float g_psq[64 * D_SZ];
__device__ float g_scale[D_SZ];
__device__ float g_shift[D_SZ];
__device__ float g_bce[HEAD_CTAS];
__device__ unsigned int g_ctr_comb;   // zero-initialized; last CTA resets
__device__ unsigned int g_ctr_head;

// ---- packed f32x2 helpers (Blackwell) ----
__device__ __forceinline__ unsigned long long pk2(float lo, float hi) {
    unsigned long long r;
    asm("mov.b64 %0, {%1, %2};" : "=l"(r) : "f"(lo), "f"(hi));
    return r;
}
__device__ __forceinline__ void upk2(unsigned long long v, float& lo, float& hi) {
    asm("mov.b64 {%0, %1}, %2;" : "=f"(lo), "=f"(hi) : "l"(v));
}
__device__ __forceinline__ unsigned long long fma2(unsigned long long a,
                                                   unsigned long long b,
                                                   unsigned long long c) {
    unsigned long long d;
    asm("fma.rn.f32x2 %0, %1, %2, %3;" : "=l"(d) : "l"(a), "l"(b), "l"(c));
    return d;
}

// ============================================================================
// K1: ragged gather + mean pool.  One CTA per batch row, 256 threads.
// (Exact R5 form: measured at the LTS chip-throughput wall, ~35us.)
// ============================================================================
__global__ void __launch_bounds__(256) pool_kernel(const int* __restrict__ tokens,
                                                   const int* __restrict__ lengths,
                                                   const float* __restrict__ emb) {
    const int b = blockIdx.x;
    const int tid = threadIdx.x;
    __shared__ int s_tok[L_SZ];
    const int len = lengths[b];
    for (int i = tid; i < len; i += 256) s_tok[i] = tokens[b * L_SZ + i];
    __syncthreads();

    const int sub = tid >> 6;   // 0..3 : which token of the group of 4
    const int q   = tid & 63;   // which float4 of the 256-wide embedding

    float4 acc = make_float4(0.f, 0.f, 0.f, 0.f);
    #pragma unroll 4
    for (int l = sub; l < len; l += 4) {
        const float4* row = reinterpret_cast<const float4*>(emb + (size_t)s_tok[l] * D_SZ);
        float4 v = __ldg(row + q);
        acc.x += v.x; acc.y += v.y; acc.z += v.z; acc.w += v.w;
    }

    __shared__ float4 s_acc[256];
    s_acc[tid] = acc;
    __syncthreads();
    if (tid < 64) {
        float4 a = s_acc[tid];
        float4 c = s_acc[tid + 64];
        float4 d = s_acc[tid + 128];
        float4 e = s_acc[tid + 192];
        const float inv = 1.0f / (float)len;
        float4 r;
        r.x = (a.x + c.x + d.x + e.x) * inv;
        r.y = (a.y + c.y + d.y + e.y) * inv;
        r.z = (a.z + c.z + d.z + e.z) * inv;
        r.w = (a.w + c.w + d.w + e.w) * inv;
        reinterpret_cast<float4*>(g_pooled + (size_t)b * D_SZ)[tid] = r;
    }
}

// ============================================================================
// K2: split-K GEMM partials.  zp[ks] = pooled[:, ks*128:+128] @ W1[:, same]^T.
// Tile 128x128, 256 threads, 8x8 per thread (rows/cols split as q and q+64),
// BK=8.  4 conflict-free LDS.128 feed 32 FFMA2 per k-step.
// grid = (64 tiles, 2 k-slices).
// ============================================================================
__global__ void __launch_bounds__(256) gemm_split_kernel(const float* __restrict__ W1) {
    __shared__ float As[8][132];   // As[k][m]; 132-pad => conflict-free STS+LDS
    __shared__ float Bs[8][132];   // Bs[k][n]

    const int tid = threadIdx.x;
    const int tx = tid & 15;            // n-group
    const int ty = tid >> 4;            // m-group
    const int tile = blockIdx.x;        // 0..63
    const int m0 = (tile >> 1) * 128;
    const int n0 = (tile & 1) * 128;
    const int kb = blockIdx.y * 128;    // k-slice base

    const int lrow = tid >> 1;          // 0..127 (load row)
    const int lkq = (tid & 1) << 2;     // 0 or 4 (load k offset)

    unsigned long long c2[8][4];
    #pragma unroll
    for (int i = 0; i < 8; i++)
        #pragma unroll
        for (int j = 0; j < 4; j++) c2[i][j] = 0ull;

    for (int k0 = 0; k0 < 128; k0 += 8) {
        float4 av = *reinterpret_cast<const float4*>(g_pooled + (size_t)(m0 + lrow) * D_SZ + kb + k0 + lkq);
        float4 bv = *reinterpret_cast<const float4*>(W1 + (size_t)(n0 + lrow) * D_SZ + kb + k0 + lkq);
        As[lkq + 0][lrow] = av.x; As[lkq + 1][lrow] = av.y;
        As[lkq + 2][lrow] = av.z; As[lkq + 3][lrow] = av.w;
        Bs[lkq + 0][lrow] = bv.x; Bs[lkq + 1][lrow] = bv.y;
        Bs[lkq + 2][lrow] = bv.z; Bs[lkq + 3][lrow] = bv.w;
        __syncthreads();

        #pragma unroll
        for (int k = 0; k < 8; k++) {
            float4 a0 = *reinterpret_cast<const float4*>(&As[k][ty << 2]);
            float4 a1 = *reinterpret_cast<const float4*>(&As[k][64 + (ty << 2)]);
            ulonglong2 b0 = *reinterpret_cast<const ulonglong2*>(&Bs[k][tx << 2]);
            ulonglong2 b1 = *reinterpret_cast<const ulonglong2*>(&Bs[k][64 + (tx << 2)]);
            float aa[8] = {a0.x, a0.y, a0.z, a0.w, a1.x, a1.y, a1.z, a1.w};
            #pragma unroll
            for (int i = 0; i < 8; i++) {
                unsigned long long ad = pk2(aa[i], aa[i]);
                c2[i][0] = fma2(ad, b0.x, c2[i][0]);
                c2[i][1] = fma2(ad, b0.y, c2[i][1]);
                c2[i][2] = fma2(ad, b1.x, c2[i][2]);
                c2[i][3] = fma2(ad, b1.y, c2[i][3]);
            }
        }
        __syncthreads();
    }

    float* zp = blockIdx.y ? g_zp1 : g_zp0;
    #pragma unroll
    for (int i = 0; i < 8; i++) {
        const int row = m0 + ((i < 4) ? ((ty << 2) + i) : (64 + (ty << 2) + i - 4));
        float v[8];
        upk2(c2[i][0], v[0], v[1]);
        upk2(c2[i][1], v[2], v[3]);
        upk2(c2[i][2], v[4], v[5]);
        upk2(c2[i][3], v[6], v[7]);
        float4 lo = make_float4(v[0], v[1], v[2], v[3]);
        float4 hi = make_float4(v[4], v[5], v[6], v[7]);
        *reinterpret_cast<float4*>(zp + (size_t)row * D_SZ + n0 + (tx << 2)) = lo;
        *reinterpret_cast<float4*>(zp + (size_t)row * D_SZ + n0 + 64 + (tx << 2)) = hi;
    }
}

// ============================================================================
// K3: combine: z = zp0 + zp1 + b1, BN partial stats per 64-row chunk,
// last-CTA finalize (mu/var -> scale/shift).  grid = 64, 256 threads.
// ============================================================================
__global__ void __launch_bounds__(256) combine_kernel(const float* __restrict__ b1,
                                                      const float* __restrict__ gamma,
                                                      const float* __restrict__ beta) {
    const int tid = threadIdx.x;
    const int chunk = blockIdx.x;       // 0..63
    const int r0 = chunk * 64;
    const int c4 = tid & 63;            // float4 column index
    const int rg = tid >> 6;            // 0..3 row group

    const float4 bias = reinterpret_cast<const float4*>(b1)[c4];
    float4 s = make_float4(0.f, 0.f, 0.f, 0.f);
    float4 sq = make_float4(0.f, 0.f, 0.f, 0.f);

    #pragma unroll 4
    for (int it = 0; it < 16; it++) {
        const int row = r0 + rg * 16 + it;
        const size_t off = (size_t)row * D_SZ + c4 * 4;
        float4 p = *reinterpret_cast<const float4*>(g_zp0 + off);
        float4 q = *reinterpret_cast<const float4*>(g_zp1 + off);
        float4 z;
        z.x = p.x + q.x + bias.x; z.y = p.y + q.y + bias.y;
        z.z = p.z + q.z + bias.z; z.w = p.w + q.w + bias.w;
        *reinterpret_cast<float4*>(g_z + off) = z;
        s.x += z.x; s.y += z.y; s.z += z.z; s.w += z.w;
        sq.x = fmaf(z.x, z.x, sq.x); sq.y = fmaf(z.y, z.y, sq.y);
        sq.z = fmaf(z.z, z.z, sq.z); sq.w = fmaf(z.w, z.w, sq.w);
    }

    __shared__ float4 rs[4][64];
    __shared__ float4 rq[4][64];
    rs[rg][c4] = s;
    rq[rg][c4] = sq;
    __syncthreads();
    if (tid < 64) {
        float4 S = rs[0][tid], Q = rq[0][tid];
        #pragma unroll
        for (int j = 1; j < 4; j++) {
            S.x += rs[j][tid].x; S.y += rs[j][tid].y; S.z += rs[j][tid].z; S.w += rs[j][tid].w;
            Q.x += rq[j][tid].x; Q.y += rq[j][tid].y; Q.z += rq[j][tid].z; Q.w += rq[j][tid].w;
        }
        reinterpret_cast<float4*>(g_psum + chunk * D_SZ)[tid] = S;
        reinterpret_cast<float4*>(g_psq + chunk * D_SZ)[tid] = Q;
    }

    // ---- last-CTA finalize: deterministic fixed-order sums ----
    __threadfence();
    __shared__ unsigned int s_ticket;
    if (tid == 0) s_ticket = atomicAdd(&g_ctr_comb, 1u);
    __syncthreads();
    if (s_ticket == 63u) {
        if (tid == 0) g_ctr_comb = 0u;   // reset for next graph replay
        const int d = tid;               // 256 threads == 256 features
        float ss = 0.f, qq = 0.f;
        #pragma unroll 8
        for (int i = 0; i < 64; i++) {
            ss += g_psum[i * D_SZ + d];
            qq += g_psq[i * D_SZ + d];
        }
        const float mu = ss * kInvB;
        const float var = qq * kInvB - mu * mu;
        const float rstd = rsqrtf(var + BN_EPS);
        const float sc = gamma[d] * rstd;
        g_scale[d] = sc;
        g_shift[d] = beta[d] - mu * sc;
    }
}

// ============================================================================
// K4: h = relu(scale*z + shift); logit = h.w2 + b2; per-CTA BCE partial;
// LAST CTA reduces 512 partials (fixed order) -> out[0].
// Warp per row, 8 rows/CTA, grid = 512.
// ============================================================================
__global__ void __launch_bounds__(256) head_kernel(const float* __restrict__ w2,
                                                   const float* __restrict__ b2,
                                                   const float* __restrict__ t,
                                                   float* __restrict__ out) {
    const int tid = threadIdx.x;
    const int warp = tid >> 5;
    const int lane = tid & 31;
    const int b = blockIdx.x * 8 + warp;

    const float4* zr = reinterpret_cast<const float4*>(g_z + (size_t)b * D_SZ);
    const float4* scv = reinterpret_cast<const float4*>(g_scale);
    const float4* shv = reinterpret_cast<const float4*>(g_shift);
    const float4* wv = reinterpret_cast<const float4*>(w2);

    float p = 0.f;
    #pragma unroll
    for (int half = 0; half < 2; half++) {
        const int q = lane + half * 32;
        float4 z = zr[q];
        float4 sc = __ldg(scv + q);
        float4 sh = __ldg(shv + q);
        float4 w = __ldg(wv + q);
        float h0 = fmaxf(fmaf(sc.x, z.x, sh.x), 0.f);
        float h1 = fmaxf(fmaf(sc.y, z.y, sh.y), 0.f);
        float h2 = fmaxf(fmaf(sc.z, z.z, sh.z), 0.f);
        float h3 = fmaxf(fmaf(sc.w, z.w, sh.w), 0.f);
        p += h0 * w.x + h1 * w.y + h2 * w.z + h3 * w.w;
    }
    #pragma unroll
    for (int off = 16; off > 0; off >>= 1)
        p += __shfl_down_sync(0xffffffffu, p, off);

    __shared__ float s_bce[8];
    if (lane == 0) {
        const float logit = p + b2[0];
        out[1 + b] = logit;
        const float tv = t[b];
        s_bce[warp] = fmaxf(logit, 0.f) - logit * tv + log1pf(expf(-fabsf(logit)));
    }
    __syncthreads();
    if (tid == 0) {
        float c = 0.f;
        #pragma unroll
        for (int i = 0; i < 8; i++) c += s_bce[i];
        g_bce[blockIdx.x] = c;
    }

    // ---- last-CTA loss reduce: deterministic fixed-order tree ----
    __threadfence();
    __shared__ unsigned int s_ticket;
    if (tid == 0) s_ticket = atomicAdd(&g_ctr_head, 1u);
    __syncthreads();
    if (s_ticket == (unsigned)(HEAD_CTAS - 1)) {
        if (tid == 0) g_ctr_head = 0u;   // reset for next graph replay
        __shared__ float red[256];
        red[tid] = g_bce[tid] + g_bce[tid + 256];
        __syncthreads();
        #pragma unroll
        for (int st = 128; st > 0; st >>= 1) {
            if (tid < st) red[tid] += red[tid + st];
            __syncthreads();
        }
        if (tid == 0) out[0] = red[0] * kInvB;
    }
}

// ============================================================================
extern "C" void kernel_launch(void* const* d_in, const int* in_sizes, int n_in,
                              void* d_out, int out_size) {
    const int*   tokens  = (const int*)d_in[0];
    const int*   lengths = (const int*)d_in[1];
    const float* t       = (const float*)d_in[2];
    const float* emb     = (const float*)d_in[3];
    const float* W1      = (const float*)d_in[4];
    const float* b1      = (const float*)d_in[5];
    const float* gamma   = (const float*)d_in[6];
    const float* beta    = (const float*)d_in[7];
    const float* w2      = (const float*)d_in[8];
    const float* b2      = (const float*)d_in[9];
    float* out = (float*)d_out;

    pool_kernel<<<B_SZ, 256>>>(tokens, lengths, emb);
    gemm_split_kernel<<<dim3(64, 2), 256>>>(W1);
    combine_kernel<<<64, 256>>>(b1, gamma, beta);
    head_kernel<<<HEAD_CTAS, 256>>>(w2, b2, t, out);
}

// round 16
// speedup vs baseline: 1.0862x; 1.0272x over previous
#include <cuda_runtime.h>
#include <math.h>

// Problem constants (fixed shapes from reference setup_inputs)
#define B_SZ 4096
#define L_SZ 200
#define D_SZ 256
#define HEAD_CTAS (B_SZ / 8)        // 512
#define N_TILES 64                  // 32 m-blocks x 2 n-blocks (128x128 tiles)
static __device__ __constant__ float kInvB = 1.0f / (float)B_SZ;
#define BN_EPS 1e-5f

// ---- scratch (device globals; no allocation allowed) ----
__device__ float g_pooled[(size_t)B_SZ * D_SZ];   // 4 MB
__device__ float g_z[(size_t)B_SZ * D_SZ];        // 4 MB
__device__ float g_zp0[(size_t)B_SZ * D_SZ];      // 4 MB (k-slice 0 partial)
__device__ float g_zp1[(size_t)B_SZ * D_SZ];      // 4 MB (k-slice 1 partial)
__device__ float g_psum[32 * D_SZ];               // per-m-block column sums
__device__ float g_psq[32 * D_SZ];
__device__ float g_scale[D_SZ];
__device__ float g_shift[D_SZ];
__device__ float g_bce[HEAD_CTAS];
__device__ unsigned int g_tile_ctr[N_TILES];      // per-tile tickets (ticket-1 CTA resets)
__device__ unsigned int g_ctr_stats;              // finalize ticket (last resets)
__device__ unsigned int g_ctr_head;

// ---- packed f32x2 helpers (Blackwell) ----
__device__ __forceinline__ unsigned long long pk2(float lo, float hi) {
    unsigned long long r;
    asm("mov.b64 %0, {%1, %2};" : "=l"(r) : "f"(lo), "f"(hi));
    return r;
}
__device__ __forceinline__ void upk2(unsigned long long v, float& lo, float& hi) {
    asm("mov.b64 {%0, %1}, %2;" : "=f"(lo), "=f"(hi) : "l"(v));
}
__device__ __forceinline__ unsigned long long fma2(unsigned long long a,
                                                   unsigned long long b,
                                                   unsigned long long c) {
    unsigned long long d;
    asm("fma.rn.f32x2 %0, %1, %2, %3;" : "=l"(d) : "l"(a), "l"(b), "l"(c));
    return d;
}

// ============================================================================
// K1: ragged gather + mean pool.  One CTA per batch row, 256 threads.
// (Exact R5 form: measured at the LTS chip-throughput wall, ~35us. FROZEN.)
// ============================================================================
__global__ void __launch_bounds__(256) pool_kernel(const int* __restrict__ tokens,
                                                   const int* __restrict__ lengths,
                                                   const float* __restrict__ emb) {
    const int b = blockIdx.x;
    const int tid = threadIdx.x;
    __shared__ int s_tok[L_SZ];
    const int len = lengths[b];
    for (int i = tid; i < len; i += 256) s_tok[i] = tokens[b * L_SZ + i];
    __syncthreads();

    const int sub = tid >> 6;   // 0..3 : which token of the group of 4
    const int q   = tid & 63;   // which float4 of the 256-wide embedding

    float4 acc = make_float4(0.f, 0.f, 0.f, 0.f);
    #pragma unroll 4
    for (int l = sub; l < len; l += 4) {
        const float4* row = reinterpret_cast<const float4*>(emb + (size_t)s_tok[l] * D_SZ);
        float4 v = __ldg(row + q);
        acc.x += v.x; acc.y += v.y; acc.z += v.z; acc.w += v.w;
    }

    __shared__ float4 s_acc[256];
    s_acc[tid] = acc;
    __syncthreads();
    if (tid < 64) {
        float4 a = s_acc[tid];
        float4 c = s_acc[tid + 64];
        float4 d = s_acc[tid + 128];
        float4 e = s_acc[tid + 192];
        const float inv = 1.0f / (float)len;
        float4 r;
        r.x = (a.x + c.x + d.x + e.x) * inv;
        r.y = (a.y + c.y + d.y + e.y) * inv;
        r.z = (a.z + c.z + d.z + e.z) * inv;
        r.w = (a.w + c.w + d.w + e.w) * inv;
        reinterpret_cast<float4*>(g_pooled + (size_t)b * D_SZ)[tid] = r;
    }
}

// ============================================================================
// K2: split-K GEMM + spin-free fused combine + BN stats + finalize.
// Each k-slice CTA stores its partial to ITS OWN buffer, fences, takes a
// ticket.  Ticket 0 exits.  Ticket 1 is guaranteed (fence-before-add) to see
// the other slice's partial; it combines (2-term commutative sum -> bitwise
// deterministic), writes z, computes tile stats; last stats CTA finalizes.
// NO wait loops anywhere; counters self-reset with no pending adds.
// ============================================================================
__global__ void __launch_bounds__(256) gemm_fused_kernel(const float* __restrict__ W1,
                                                         const float* __restrict__ b1,
                                                         const float* __restrict__ gamma,
                                                         const float* __restrict__ beta) {
    __shared__ float As[8][132];   // As[k][m]; 132-pad => conflict-free STS+LDS
    __shared__ float Bs[8][132];   // Bs[k][n]

    const int tid = threadIdx.x;
    const int tx = tid & 15;            // n-group
    const int ty = tid >> 4;            // m-group
    const int tile = blockIdx.x;        // 0..63
    const int m0 = (tile >> 1) * 128;
    const int n0 = (tile & 1) * 128;
    const int slice = blockIdx.y;       // 0 or 1
    const int kb = slice * 128;         // k-slice base

    const int lrow = tid >> 1;          // 0..127 (load row)
    const int lkq = (tid & 1) << 2;     // 0 or 4 (load k offset)

    unsigned long long c2[8][4];
    #pragma unroll
    for (int i = 0; i < 8; i++)
        #pragma unroll
        for (int j = 0; j < 4; j++) c2[i][j] = 0ull;

    for (int k0 = 0; k0 < 128; k0 += 8) {
        float4 av = *reinterpret_cast<const float4*>(g_pooled + (size_t)(m0 + lrow) * D_SZ + kb + k0 + lkq);
        float4 bv = *reinterpret_cast<const float4*>(W1 + (size_t)(n0 + lrow) * D_SZ + kb + k0 + lkq);
        As[lkq + 0][lrow] = av.x; As[lkq + 1][lrow] = av.y;
        As[lkq + 2][lrow] = av.z; As[lkq + 3][lrow] = av.w;
        Bs[lkq + 0][lrow] = bv.x; Bs[lkq + 1][lrow] = bv.y;
        Bs[lkq + 2][lrow] = bv.z; Bs[lkq + 3][lrow] = bv.w;
        __syncthreads();

        #pragma unroll
        for (int k = 0; k < 8; k++) {
            float4 a0 = *reinterpret_cast<const float4*>(&As[k][ty << 2]);
            float4 a1 = *reinterpret_cast<const float4*>(&As[k][64 + (ty << 2)]);
            ulonglong2 b0 = *reinterpret_cast<const ulonglong2*>(&Bs[k][tx << 2]);
            ulonglong2 b1v = *reinterpret_cast<const ulonglong2*>(&Bs[k][64 + (tx << 2)]);
            float aa[8] = {a0.x, a0.y, a0.z, a0.w, a1.x, a1.y, a1.z, a1.w};
            #pragma unroll
            for (int i = 0; i < 8; i++) {
                unsigned long long ad = pk2(aa[i], aa[i]);
                c2[i][0] = fma2(ad, b0.x, c2[i][0]);
                c2[i][1] = fma2(ad, b0.y, c2[i][1]);
                c2[i][2] = fma2(ad, b1v.x, c2[i][2]);
                c2[i][3] = fma2(ad, b1v.y, c2[i][3]);
            }
        }
        __syncthreads();
    }

    // unpack accumulators
    float v[8][8];
    #pragma unroll
    for (int i = 0; i < 8; i++) {
        upk2(c2[i][0], v[i][0], v[i][1]);
        upk2(c2[i][1], v[i][2], v[i][3]);
        upk2(c2[i][2], v[i][4], v[i][5]);
        upk2(c2[i][3], v[i][6], v[i][7]);
    }

    // store partial to THIS slice's buffer
    float* mine = slice ? g_zp1 : g_zp0;
    #pragma unroll
    for (int i = 0; i < 8; i++) {
        const int row = m0 + ((i < 4) ? ((ty << 2) + i) : (64 + (ty << 2) + i - 4));
        float4 lo = make_float4(v[i][0], v[i][1], v[i][2], v[i][3]);
        float4 hi = make_float4(v[i][4], v[i][5], v[i][6], v[i][7]);
        *reinterpret_cast<float4*>(mine + (size_t)row * D_SZ + n0 + (tx << 2)) = lo;
        *reinterpret_cast<float4*>(mine + (size_t)row * D_SZ + n0 + 64 + (tx << 2)) = hi;
    }
    __threadfence();
    __syncthreads();

    // ---- per-tile ticket: exactly one add per CTA, no waiting ----
    __shared__ unsigned int s_ticket;
    if (tid == 0) s_ticket = atomicAdd(&g_tile_ctr[tile], 1u);
    __syncthreads();
    if (s_ticket == 0u) return;          // first finisher done

    if (tid == 0) g_tile_ctr[tile] = 0u; // both adds landed; safe reset
    __threadfence();                     // acquire side: order partial reads

    // second finisher: combine own registers + other slice's partial + bias
    const float* other = slice ? g_zp0 : g_zp1;
    const float4 biasLo = *reinterpret_cast<const float4*>(b1 + n0 + (tx << 2));
    const float4 biasHi = *reinterpret_cast<const float4*>(b1 + n0 + 64 + (tx << 2));
    float cs[8] = {0,0,0,0,0,0,0,0};
    float cq[8] = {0,0,0,0,0,0,0,0};
    #pragma unroll
    for (int i = 0; i < 8; i++) {
        const int row = m0 + ((i < 4) ? ((ty << 2) + i) : (64 + (ty << 2) + i - 4));
        float4 pLo = *reinterpret_cast<const float4*>(other + (size_t)row * D_SZ + n0 + (tx << 2));
        float4 pHi = *reinterpret_cast<const float4*>(other + (size_t)row * D_SZ + n0 + 64 + (tx << 2));
        float zz[8];
        zz[0] = v[i][0] + pLo.x + biasLo.x; zz[1] = v[i][1] + pLo.y + biasLo.y;
        zz[2] = v[i][2] + pLo.z + biasLo.z; zz[3] = v[i][3] + pLo.w + biasLo.w;
        zz[4] = v[i][4] + pHi.x + biasHi.x; zz[5] = v[i][5] + pHi.y + biasHi.y;
        zz[6] = v[i][6] + pHi.z + biasHi.z; zz[7] = v[i][7] + pHi.w + biasHi.w;
        #pragma unroll
        for (int c = 0; c < 8; c++) {
            cs[c] += zz[c];
            cq[c] = fmaf(zz[c], zz[c], cq[c]);
        }
        float4 lo = make_float4(zz[0], zz[1], zz[2], zz[3]);
        float4 hi = make_float4(zz[4], zz[5], zz[6], zz[7]);
        *reinterpret_cast<float4*>(g_z + (size_t)row * D_SZ + n0 + (tx << 2)) = lo;
        *reinterpret_cast<float4*>(g_z + (size_t)row * D_SZ + n0 + 64 + (tx << 2)) = hi;
    }

    // tile column stats: reduce the 16 ty-groups per column (128 cols)
    __shared__ float s_sum[16][128];
    __shared__ float s_sq[16][128];
    #pragma unroll
    for (int c = 0; c < 4; c++) {
        s_sum[ty][(tx << 2) + c] = cs[c];
        s_sq[ty][(tx << 2) + c] = cq[c];
        s_sum[ty][64 + (tx << 2) + c] = cs[c + 4];
        s_sq[ty][64 + (tx << 2) + c] = cq[c + 4];
    }
    __syncthreads();
    if (tid < 128) {
        float s = 0.f, sq = 0.f;
        #pragma unroll
        for (int j = 0; j < 16; j++) { s += s_sum[j][tid]; sq += s_sq[j][tid]; }
        g_psum[(tile >> 1) * D_SZ + n0 + tid] = s;
        g_psq[(tile >> 1) * D_SZ + n0 + tid] = sq;
    }

    // ---- global finalize ticket: 64 stat-writing CTAs, last one finalizes ----
    __threadfence();
    __shared__ unsigned int s_fin;
    if (tid == 0) s_fin = atomicAdd(&g_ctr_stats, 1u);
    __syncthreads();
    if (s_fin == (unsigned)(N_TILES - 1)) {
        if (tid == 0) g_ctr_stats = 0u;   // all 64 adds landed; safe reset
        const int d = tid;                // 256 threads == 256 features
        float ss = 0.f, qq = 0.f;
        #pragma unroll 8
        for (int i = 0; i < 32; i++) {
            ss += g_psum[i * D_SZ + d];
            qq += g_psq[i * D_SZ + d];
        }
        const float mu = ss * kInvB;
        const float var = qq * kInvB - mu * mu;
        const float rstd = rsqrtf(var + BN_EPS);
        const float sc = gamma[d] * rstd;
        g_scale[d] = sc;
        g_shift[d] = beta[d] - mu * sc;
    }
}

// ============================================================================
// K3: h = relu(scale*z + shift); logit = h.w2 + b2; per-CTA BCE partial;
// LAST CTA reduces 512 partials (fixed order) -> out[0].
// Warp per row, 8 rows/CTA, grid = 512.
// ============================================================================
__global__ void __launch_bounds__(256) head_kernel(const float* __restrict__ w2,
                                                   const float* __restrict__ b2,
                                                   const float* __restrict__ t,
                                                   float* __restrict__ out) {
    const int tid = threadIdx.x;
    const int warp = tid >> 5;
    const int lane = tid & 31;
    const int b = blockIdx.x * 8 + warp;

    const float4* zr = reinterpret_cast<const float4*>(g_z + (size_t)b * D_SZ);
    const float4* scv = reinterpret_cast<const float4*>(g_scale);
    const float4* shv = reinterpret_cast<const float4*>(g_shift);
    const float4* wv = reinterpret_cast<const float4*>(w2);

    float p = 0.f;
    #pragma unroll
    for (int half = 0; half < 2; half++) {
        const int q = lane + half * 32;
        float4 z = zr[q];
        float4 sc = __ldg(scv + q);
        float4 sh = __ldg(shv + q);
        float4 w = __ldg(wv + q);
        float h0 = fmaxf(fmaf(sc.x, z.x, sh.x), 0.f);
        float h1 = fmaxf(fmaf(sc.y, z.y, sh.y), 0.f);
        float h2 = fmaxf(fmaf(sc.z, z.z, sh.z), 0.f);
        float h3 = fmaxf(fmaf(sc.w, z.w, sh.w), 0.f);
        p += h0 * w.x + h1 * w.y + h2 * w.z + h3 * w.w;
    }
    #pragma unroll
    for (int off = 16; off > 0; off >>= 1)
        p += __shfl_down_sync(0xffffffffu, p, off);

    __shared__ float s_bce[8];
    if (lane == 0) {
        const float logit = p + b2[0];
        out[1 + b] = logit;
        const float tv = t[b];
        s_bce[warp] = fmaxf(logit, 0.f) - logit * tv + log1pf(expf(-fabsf(logit)));
    }
    __syncthreads();
    if (tid == 0) {
        float c = 0.f;
        #pragma unroll
        for (int i = 0; i < 8; i++) c += s_bce[i];
        g_bce[blockIdx.x] = c;
    }

    // ---- last-CTA loss reduce: deterministic fixed-order tree ----
    __threadfence();
    __shared__ unsigned int s_ticket;
    if (tid == 0) s_ticket = atomicAdd(&g_ctr_head, 1u);
    __syncthreads();
    if (s_ticket == (unsigned)(HEAD_CTAS - 1)) {
        if (tid == 0) g_ctr_head = 0u;   // all 512 adds landed; safe reset
        __shared__ float red[256];
        red[tid] = g_bce[tid] + g_bce[tid + 256];
        __syncthreads();
        #pragma unroll
        for (int st = 128; st > 0; st >>= 1) {
            if (tid < st) red[tid] += red[tid + st];
            __syncthreads();
        }
        if (tid == 0) out[0] = red[0] * kInvB;
    }
}

// ============================================================================
extern "C" void kernel_launch(void* const* d_in, const int* in_sizes, int n_in,
                              void* d_out, int out_size) {
    const int*   tokens  = (const int*)d_in[0];
    const int*   lengths = (const int*)d_in[1];
    const float* t       = (const float*)d_in[2];
    const float* emb     = (const float*)d_in[3];
    const float* W1      = (const float*)d_in[4];
    const float* b1      = (const float*)d_in[5];
    const float* gamma   = (const float*)d_in[6];
    const float* beta    = (const float*)d_in[7];
    const float* w2      = (const float*)d_in[8];
    const float* b2      = (const float*)d_in[9];
    float* out = (float*)d_out;

    pool_kernel<<<B_SZ, 256>>>(tokens, lengths, emb);
    gemm_fused_kernel<<<dim3(N_TILES, 2), 256>>>(W1, b1, gamma, beta);
    head_kernel<<<HEAD_CTAS, 256>>>(w2, b2, t, out);
}